// round 12
// baseline (speedup 1.0000x reference)
#include <cuda_runtime.h>
#include <cstdint>
#include <cfloat>
#include <math.h>

// ---------------------------------------------------------------------------
// Problem constants
//   B=2, M=256 -> 512 groups, 64 points/group, KNN=16, CIN=64 (3 xyz + 61 feat)
//   MLPS=[64,128], SUMM=192, CALIB=64, EXP=[256,512], OUT=256
// ---------------------------------------------------------------------------

// Scratch (static device arrays; no runtime allocation)
__device__ float d_x_[512 * 64 * 64];      // input panel  [g][c(64)][n(64)]
__device__ int   d_idx_[512 * 64 * 16];    // knn indices  [g][n][k]
__device__ float d_big_[512 * 256 * 64];   // exp1 out
__device__ float d_cat_[512 * 192 * 64];   // concat features [g][c(192)][n]
__device__ float d_gt_[2 * 512 * 256];     // pooled vector, [b][c(512)][m(256)]
__device__ float d_x1_[2 * 256 * 256];     // after red+bn1
__device__ float d_h_[2 * 256 * 256];      // sc1 out

// All weights, transposed to [c][o] (plain float — o-pairs are natural f32x2).
//   ws1   @0       64c x 128o  ([W1(64) ; W2-W1(64)])
//   ws2   @8192    64c x 256o  per-block interleave: o'=half*128+r,
//                              r<64 -> W1 row half*64+r ; r>=64 -> (W2-W1) row half*64+(r-64)
//   cal1  @24576  192c x  64o
//   cal2  @36864   64c x 192o
//   exp1  @49152  192c x 256o
//   exp2  @98304  256c x 512o
//   red   @229376 512c x 256o
//   sc1   @360448 256c x 256o
//   sc2   @425984 256c x 256o
#define WP_WS1  0
#define WP_WS2  8192
#define WP_CAL1 24576
#define WP_CAL2 36864
#define WP_EXP1 49152
#define WP_EXP2 98304
#define WP_RED  229376
#define WP_SC1  360448
#define WP_SC2  425984
#define WP_TOT  491520
__device__ float d_wt_[WP_TOT];

// ---------------------------------------------------------------------------
// f32x2 packed-FMA + cp.async helpers
// ---------------------------------------------------------------------------
__device__ __forceinline__ unsigned long long pack2(float v) {
    unsigned long long r;
    asm("mov.b64 %0, {%1, %1};" : "=l"(r) : "r"(__float_as_uint(v)));
    return r;
}
__device__ __forceinline__ void ffma2(unsigned long long& d,
                                      unsigned long long a, unsigned long long b) {
    asm("fma.rn.f32x2 %0, %1, %2, %0;" : "+l"(d) : "l"(a), "l"(b));
}
__device__ __forceinline__ float lo2(unsigned long long v) { return __uint_as_float((unsigned)v); }
__device__ __forceinline__ float hi2(unsigned long long v) { return __uint_as_float((unsigned)(v >> 32)); }

__device__ __forceinline__ void cp16(unsigned int dst, const void* src) {
    asm volatile("cp.async.cg.shared.global [%0], [%1], 16;" :: "r"(dst), "l"(src));
}
__device__ __forceinline__ void cp_commit() { asm volatile("cp.async.commit_group;"); }
template<int N> __device__ __forceinline__ void cp_wait() {
    asm volatile("cp.async.wait_group %0;" :: "n"(N));
}

// ---------------------------------------------------------------------------
// K0 (x2 launches): transpose ALL weights into d_wt_ ([c][o], plain float).
// ---------------------------------------------------------------------------
__global__ void prep_pack(const float* __restrict__ e1w, const float* __restrict__ e2w,
                          const float* __restrict__ cal1w, const float* __restrict__ cal2w,
                          const float* __restrict__ exp1w, const float* __restrict__ exp2w,
                          const float* __restrict__ redw, const float* __restrict__ sc1w,
                          const float* __restrict__ sc2w, int part) {
    int i = blockIdx.x * blockDim.x + threadIdx.x + (part ? WP_EXP2 : 0);
    if (part == 0) {
        if (i >= WP_EXP2) return;
    } else {
        if (i >= WP_TOT) return;
    }
    float v;
    if (i < WP_WS2) {                 // ws1: O=128, C=64
        int l = i - WP_WS1, c = l >> 7, o = l & 127;
        v = (o < 64) ? e1w[o * 128 + c]
                     : e1w[(o - 64) * 128 + 64 + c] - e1w[(o - 64) * 128 + c];
    } else if (i < WP_CAL1) {         // ws2: O=256 (per-block [U;T] interleave)
        int l = i - WP_WS2, c = l >> 8, op = l & 255;
        int half = op >> 7, r = op & 127;
        int row = half * 64 + (r & 63);
        v = (r < 64) ? e2w[row * 128 + c]
                     : e2w[row * 128 + 64 + c] - e2w[row * 128 + c];
    } else if (i < WP_CAL2) {         // cal1: O=64, C=192
        int l = i - WP_CAL1, c = l >> 6, o = l & 63;
        v = cal1w[o * 192 + c];
    } else if (i < WP_EXP1) {         // cal2: O=192, C=64
        int l = i - WP_CAL2, c = l / 192, o = l % 192;
        v = cal2w[o * 64 + c];
    } else if (i < WP_EXP2) {         // exp1: O=256, C=192
        int l = i - WP_EXP1, c = l >> 8, o = l & 255;
        v = exp1w[o * 192 + c];
    } else if (i < WP_RED) {          // exp2: O=512, C=256
        int l = i - WP_EXP2, c = l >> 9, o = l & 511;
        v = exp2w[o * 256 + c];
    } else if (i < WP_SC1) {          // red: O=256, C=512
        int l = i - WP_RED, c = l >> 8, o = l & 255;
        v = redw[o * 512 + c];
    } else if (i < WP_SC2) {          // sc1: O=256, C=256
        int l = i - WP_SC1, c = l >> 8, o = l & 255;
        v = sc1w[o * 256 + c];
    } else {                          // sc2: O=256, C=256
        int l = i - WP_SC2, c = l >> 8, o = l & 255;
        v = sc2w[o * 256 + c];
    }
    d_wt_[i] = v;
}

// ---------------------------------------------------------------------------
// K1: build input panel d_x (xyz+feats transposed) + 16-NN per point.
// ---------------------------------------------------------------------------
__global__ void knn_kernel(const float* __restrict__ xyz, const float* __restrict__ feats) {
    int g = blockIdx.x, t = threadIdx.x;
    __shared__ float px[64], py[64], pz[64], xx[64];
    __shared__ float sbuf[64 * 65];

    int b3 = (g * 64 + t) * 3;
    float ax = xyz[b3 + 0], ay = xyz[b3 + 1], az = xyz[b3 + 2];
    px[t] = ax; py[t] = ay; pz[t] = az;
    xx[t] = ax * ax + ay * ay + az * az;

    float* xg = d_x_ + (size_t)g * 4096;
    xg[0 * 64 + t] = ax; xg[1 * 64 + t] = ay; xg[2 * 64 + t] = az;

    const float* fg = feats + (size_t)g * 64 * 61;
    for (int i = 0; i < 61; i++) sbuf[i * 64 + t] = fg[i * 64 + t];
    __syncthreads();
    for (int c = 0; c < 61; c++) xg[(3 + c) * 64 + t] = sbuf[t * 61 + c];
    __syncthreads();

    float* row = &sbuf[t * 65];
    float xn = xx[t];
    for (int m = 0; m < 64; m++)
        row[m] = 2.0f * (ax * px[m] + ay * py[m] + az * pz[m]) - xn - xx[m];

    // top-16 by selection (only the SET matters; max-over-k is order-invariant)
    int* ig = d_idx_ + (g * 64 + t) * 16;
    for (int k = 0; k < 16; k++) {
        float best = -FLT_MAX; int bi = 0;
        for (int m = 0; m < 64; m++) {
            float v = row[m];
            if (v > best) { best = v; bi = m; }
        }
        ig[k] = bi;
        row[bi] = -FLT_MAX;
    }
}

// ---------------------------------------------------------------------------
// K_calib: fused cal1 -> bn/relu -> cal2 -> sigmoid gate (in-place on d_cat).
// One block per group. GEMM1: 64o x 64n, CIN=192 (pipelined).
// GEMM2: 3 passes of 64o, CIN=64, X = Cs resident in smem.
// ---------------------------------------------------------------------------
__global__ void __launch_bounds__(256, 4)
calib_kernel(float* __restrict__ cat,
             const float* __restrict__ c1g, const float* __restrict__ c1b,
             const float* __restrict__ c2bias) {
    __shared__ __align__(16) float XsP[3 * 16 * 64];
    __shared__ __align__(16) float WsP[3 * 16 * 64];
    __shared__ __align__(16) float Cs[64 * 64];

    const int g = blockIdx.x, t = threadIdx.x;
    const int tn = t & 15, to = t >> 4;
    const int cr = t >> 4, wc4 = (t & 15) << 2;
    const unsigned int xs_s = (unsigned int)__cvta_generic_to_shared(XsP);
    const unsigned int ws_s = (unsigned int)__cvta_generic_to_shared(WsP);
    const float* Xg = cat + (size_t)g * 12288;
    const float* W1 = d_wt_ + WP_CAL1;   // [c(192)][64]
    const float* W2 = d_wt_ + WP_CAL2;   // [c(64)][192]
    const float INVS = rsqrtf(1.0f + 1e-5f);

    // ---- GEMM1: CIN=192 -> 12 chunks ----
    unsigned long long a1[2][4];
    #pragma unroll
    for (int p = 0; p < 2; p++)
        #pragma unroll
        for (int j = 0; j < 4; j++) a1[p][j] = 0ull;

    auto pf1 = [&](int cb, int st) {
        if (cb < 12) {
            int c0 = cb << 4;
            cp16(xs_s + (unsigned int)(st * 1024 + cr * 64 + wc4) * 4,
                 Xg + (size_t)(c0 + cr) * 64 + wc4);
            cp16(ws_s + (unsigned int)(st * 1024 + cr * 64 + wc4) * 4,
                 W1 + (size_t)(c0 + cr) * 64 + wc4);
        }
        cp_commit();
    };
    pf1(0, 0); pf1(1, 1);
    int st = 0;
    for (int cb = 0; cb < 12; cb++) {
        cp_wait<1>();
        __syncthreads();
        pf1(cb + 2, (st + 2) % 3);
        #pragma unroll
        for (int c = 0; c < 16; c++) {
            float4 xv = *reinterpret_cast<const float4*>(&XsP[(st * 16 + c) * 64 + (tn << 2)]);
            unsigned long long xd0 = pack2(xv.x), xd1 = pack2(xv.y);
            unsigned long long xd2 = pack2(xv.z), xd3 = pack2(xv.w);
            ulonglong2 w = *reinterpret_cast<const ulonglong2*>(&WsP[(st * 16 + c) * 64 + (to << 2)]);
            ffma2(a1[0][0], w.x, xd0); ffma2(a1[0][1], w.x, xd1);
            ffma2(a1[0][2], w.x, xd2); ffma2(a1[0][3], w.x, xd3);
            ffma2(a1[1][0], w.y, xd0); ffma2(a1[1][1], w.y, xd1);
            ffma2(a1[1][2], w.y, xd2); ffma2(a1[1][3], w.y, xd3);
        }
        st = (st + 1) % 3;
    }
    // bn + relu -> Cs
    {
        float a[4][4];
        #pragma unroll
        for (int p = 0; p < 2; p++)
            #pragma unroll
            for (int j = 0; j < 4; j++) {
                a[2 * p][j]     = lo2(a1[p][j]);
                a[2 * p + 1][j] = hi2(a1[p][j]);
            }
        #pragma unroll
        for (int i = 0; i < 4; i++) {
            int o = (to << 2) + i;
            float s = c1g[o] * INVS, b = c1b[o];
            float4 v;
            v.x = fmaxf(fmaf(a[i][0], s, b), 0.0f);
            v.y = fmaxf(fmaf(a[i][1], s, b), 0.0f);
            v.z = fmaxf(fmaf(a[i][2], s, b), 0.0f);
            v.w = fmaxf(fmaf(a[i][3], s, b), 0.0f);
            *reinterpret_cast<float4*>(&Cs[o * 64 + (tn << 2)]) = v;
        }
    }
    __syncthreads();   // Cs visible; pipeline buffers free for GEMM2

    // ---- GEMM2 + gate: 12 chunks (3 passes x 4), CIN=64, X = Cs ----
    auto pf2 = [&](int q, int stg) {
        if (q < 12) {
            int pass = q >> 2, c0 = (q & 3) << 4, ooff = pass << 6;
            cp16(ws_s + (unsigned int)(stg * 1024 + cr * 64 + wc4) * 4,
                 W2 + (size_t)(c0 + cr) * 192 + ooff + wc4);
        }
        cp_commit();
    };
    pf2(0, 0); pf2(1, 1);
    st = 0;
    for (int pass = 0; pass < 3; pass++) {
        unsigned long long a2[2][4];
        #pragma unroll
        for (int p = 0; p < 2; p++)
            #pragma unroll
            for (int j = 0; j < 4; j++) a2[p][j] = 0ull;
        for (int cq = 0; cq < 4; cq++) {
            int q = pass * 4 + cq;
            cp_wait<1>();
            __syncthreads();
            pf2(q + 2, (st + 2) % 3);
            #pragma unroll
            for (int c = 0; c < 16; c++) {
                float4 xv = *reinterpret_cast<const float4*>(&Cs[((cq << 4) + c) * 64 + (tn << 2)]);
                unsigned long long xd0 = pack2(xv.x), xd1 = pack2(xv.y);
                unsigned long long xd2 = pack2(xv.z), xd3 = pack2(xv.w);
                ulonglong2 w = *reinterpret_cast<const ulonglong2*>(&WsP[(st * 16 + c) * 64 + (to << 2)]);
                ffma2(a2[0][0], w.x, xd0); ffma2(a2[0][1], w.x, xd1);
                ffma2(a2[0][2], w.x, xd2); ffma2(a2[0][3], w.x, xd3);
                ffma2(a2[1][0], w.y, xd0); ffma2(a2[1][1], w.y, xd1);
                ffma2(a2[1][2], w.y, xd2); ffma2(a2[1][3], w.y, xd3);
            }
            st = (st + 1) % 3;
        }
        // gate epilogue for this 64-output pass
        float a[4][4];
        #pragma unroll
        for (int p = 0; p < 2; p++)
            #pragma unroll
            for (int j = 0; j < 4; j++) {
                a[2 * p][j]     = lo2(a2[p][j]);
                a[2 * p + 1][j] = hi2(a2[p][j]);
            }
        int ooff = pass << 6;
        #pragma unroll
        for (int i = 0; i < 4; i++) {
            int o = ooff + (to << 2) + i;
            float bb = c2bias[o];
            size_t ob = (size_t)g * 12288 + (size_t)o * 64 + (tn << 2);
            float4 xin = *reinterpret_cast<const float4*>(&cat[ob]);
            float4 r;
            r.x = xin.x / (1.0f + expf(-(a[i][0] + bb)));
            r.y = xin.y / (1.0f + expf(-(a[i][1] + bb)));
            r.z = xin.z / (1.0f + expf(-(a[i][2] + bb)));
            r.w = xin.w / (1.0f + expf(-(a[i][3] + bb)));
            *reinterpret_cast<float4*>(&cat[ob]) = r;
        }
    }
}

// ---------------------------------------------------------------------------
// Fused GEMM, o-paired FFMA2:  out(OT o x 64col) = epi( W @ X )
// W pre-transposed [c][wO] plain float: consecutive o's ARE the f32x2 pair.
// 3-stage cp.async pipeline, one sync per 16-channel chunk.
// Epilogues: 0 raw | 1 relu(bn) | 2 sigmoid-gate | 3 relu(bn)+max-over-col
//            4 red: relu(bn)*2->bn1 | 5 bias+relu | 6 final bn2(x1+acc+b)
//            7 EdgeConv fused gather-max (OT=128: rows 0..63=U, 64..127=T)
// ---------------------------------------------------------------------------
template<int EPI, int OT>
__global__ void __launch_bounds__(256, 4)
gemm_k(const float* __restrict__ X, int imgStride, int cpi,
       const float* __restrict__ Wt, int CIN, int wO,
       float* out, int outImgStride, int outCpi, int chanOff,
       const float* p0, const float* p1, const float* p2, const float* p3,
       const float* aux) {
    constexpr int OPT = OT / 16;       // outputs per thread (8 or 4)
    constexpr int PAIRS = OPT / 2;     // f32x2 pairs per thread (4 or 2)
    constexpr int PIPE_F = 3 * 16 * 64 + 3 * 16 * OT;
    constexpr int EPI7_F = (EPI == 7) ? (4096 + 4096 + 64 * 17) : 0;
    constexpr int SM_F = PIPE_F > EPI7_F ? PIPE_F : EPI7_F;
    __shared__ __align__(16) float smbuf[SM_F];
    float* XsP = smbuf;                 // [(st*16+c)*64 + col]
    float* WsP = smbuf + 3 * 16 * 64;   // [(st*16+c)*OT + o]

    const int g = blockIdx.x;
    const int colBase = blockIdx.y << 6;
    const int oBase = blockIdx.z * OT;
    const int t = threadIdx.x;
    const int tn = t & 15, to = t >> 4;

    const float* Xg = X + (size_t)g * imgStride + colBase;

    const int cr = t >> 4;
    const int xc = (t & 15) << 2;
    const unsigned int xs_s = (unsigned int)__cvta_generic_to_shared(XsP);
    const unsigned int ws_s = (unsigned int)__cvta_generic_to_shared(WsP);
    const int nch = CIN >> 4;

    unsigned long long acc2[PAIRS][4];
    #pragma unroll
    for (int p = 0; p < PAIRS; p++)
        #pragma unroll
        for (int j = 0; j < 4; j++) acc2[p][j] = 0ull;

    auto prefetch = [&](int cb, int stg) {
        if (cb < nch) {
            const int c0 = cb << 4;
            cp16(xs_s + (unsigned int)(stg * 1024 + cr * 64 + xc) * 4,
                 Xg + (size_t)(c0 + cr) * cpi + xc);
            const float* wrow = Wt + (size_t)(c0 + cr) * wO + oBase;
            if constexpr (OT == 128) {
                const int wc = (t & 15) << 3;
                cp16(ws_s + (unsigned int)(stg * 16 * OT + cr * OT + wc) * 4, wrow + wc);
                cp16(ws_s + (unsigned int)(stg * 16 * OT + cr * OT + wc + 4) * 4, wrow + wc + 4);
            } else {
                const int wc = (t & 15) << 2;
                cp16(ws_s + (unsigned int)(stg * 16 * OT + cr * OT + wc) * 4, wrow + wc);
            }
        }
        cp_commit();
    };

    prefetch(0, 0);
    prefetch(1, 1);

    int st = 0, stn = 2;
    for (int cb = 0; cb < nch; cb++) {
        cp_wait<1>();
        __syncthreads();
        prefetch(cb + 2, stn);
        #pragma unroll
        for (int c = 0; c < 16; c++) {
            float4 xv = *reinterpret_cast<const float4*>(&XsP[(st * 16 + c) * 64 + (tn << 2)]);
            unsigned long long xd0 = pack2(xv.x), xd1 = pack2(xv.y);
            unsigned long long xd2 = pack2(xv.z), xd3 = pack2(xv.w);
            const ulonglong2* wr =
                reinterpret_cast<const ulonglong2*>(&WsP[(st * 16 + c) * OT + to * OPT]);
            unsigned long long wp[PAIRS];
            {
                ulonglong2 w0 = wr[0];
                wp[0] = w0.x; wp[1] = w0.y;
                if constexpr (PAIRS == 4) {
                    ulonglong2 w1 = wr[1];
                    wp[2] = w1.x; wp[3] = w1.y;
                }
            }
            #pragma unroll
            for (int p = 0; p < PAIRS; p++) {
                ffma2(acc2[p][0], wp[p], xd0);
                ffma2(acc2[p][1], wp[p], xd1);
                ffma2(acc2[p][2], wp[p], xd2);
                ffma2(acc2[p][3], wp[p], xd3);
            }
        }
        st = (st == 2) ? 0 : st + 1;
        stn = (stn == 2) ? 0 : stn + 1;
    }

    float acc[OPT][4];
    #pragma unroll
    for (int p = 0; p < PAIRS; p++)
        #pragma unroll
        for (int j = 0; j < 4; j++) {
            acc[2 * p][j]     = lo2(acc2[p][j]);
            acc[2 * p + 1][j] = hi2(acc2[p][j]);
        }
    const float INVS = rsqrtf(1.0f + 1e-5f);

    if constexpr (EPI == 7) {
        float* Us = smbuf;
        float* Ts = smbuf + 4096;
        int*   sidx = (int*)(smbuf + 8192);
        __syncthreads();
        #pragma unroll
        for (int i = 0; i < OPT; i++) {
            int r = to * OPT + i;
            float* dst = (r < 64) ? &Us[r * 64] : &Ts[(r - 64) * 64];
            #pragma unroll
            for (int j = 0; j < 4; j++) dst[(tn << 2) + j] = acc[i][j];
        }
        const int* idg = d_idx_ + g * 1024;
        for (int i = t; i < 1024; i += 256)
            sidx[(i >> 4) * 17 + (i & 15)] = idg[i];
        __syncthreads();

        const int bnoff = blockIdx.z << 6;
        float* outg = out + (size_t)g * outImgStride + (size_t)(chanOff + bnoff) * outCpi;
        for (int item = t; item < 4096; item += 256) {
            int o = item >> 6, n = item & 63;
            float T = Ts[o * 64 + n];
            float s = p0[bnoff + o] * INVS, b = p1[bnoff + o];
            const float* Uo = &Us[o * 64];
            const int*   ni = &sidx[n * 17];
            float m = -FLT_MAX;
            #pragma unroll
            for (int k = 0; k < 16; k++) {
                float v = fmaf(Uo[ni[k]] + T, s, b);
                m = fmaxf(m, fmaxf(v, 0.0f));
            }
            outg[o * (size_t)outCpi + n] = m;
        }
    } else if constexpr (EPI == 3) {
        float* red = smbuf;
        __syncthreads();
        #pragma unroll
        for (int i = 0; i < OPT; i++) {
            int o = oBase + to * OPT + i;
            float s = p0[o] * INVS, b = p1[o];
            float m = -FLT_MAX;
            #pragma unroll
            for (int j = 0; j < 4; j++)
                m = fmaxf(m, fmaxf(fmaf(acc[i][j], s, b), 0.0f));
            red[(to * OPT + i) * 17 + tn] = m;
        }
        __syncthreads();
        if (t < OT) {
            float m = red[t * 17];
            #pragma unroll
            for (int q = 1; q < 16; q++) m = fmaxf(m, red[t * 17 + q]);
            int bb = g >> 8, mm = g & 255;
            out[((size_t)bb * 512 + oBase + t) * 256 + mm] = m;
        }
    } else {
        #pragma unroll
        for (int i = 0; i < OPT; i++) {
            int o = oBase + to * OPT + i;
            size_t ob = (size_t)g * outImgStride + (size_t)(chanOff + o) * outCpi
                      + colBase + (tn << 2);
            if constexpr (EPI == 0) {
                #pragma unroll
                for (int j = 0; j < 4; j++) out[ob + j] = acc[i][j];
            } else if constexpr (EPI == 1) {
                float s = p0[o] * INVS, b = p1[o];
                #pragma unroll
                for (int j = 0; j < 4; j++)
                    out[ob + j] = fmaxf(fmaf(acc[i][j], s, b), 0.0f);
            } else if constexpr (EPI == 4) {
                float sr = p0[o] * INVS, br = p1[o];
                float s1 = p2[o] * INVS, b1 = p3[o];
                #pragma unroll
                for (int j = 0; j < 4; j++) {
                    float r = fmaxf(fmaf(acc[i][j], sr, br), 0.0f);
                    out[ob + j] = fmaf(2.0f * r, s1, b1);
                }
            } else if constexpr (EPI == 5) {
                float bb = p0[o];
                #pragma unroll
                for (int j = 0; j < 4; j++)
                    out[ob + j] = fmaxf(acc[i][j] + bb, 0.0f);
            } else if constexpr (EPI == 6) {
                float bb = p0[o], s2 = p1[o] * INVS, b2 = p2[o];
                #pragma unroll
                for (int j = 0; j < 4; j++) {
                    float v = acc[i][j] + bb + aux[ob + j];
                    out[ob + j] = fmaf(v, s2, b2);
                }
            }
        }
    }
}

// ---------------------------------------------------------------------------
extern "C" void kernel_launch(void* const* d_in, const int* in_sizes, int n_in,
                              void* d_out, int out_size) {
    const float* xyz       = (const float*)d_in[0];
    const float* feats     = (const float*)d_in[1];
    const float* e1_w      = (const float*)d_in[2];
    const float* e1_g      = (const float*)d_in[3];
    const float* e1_b      = (const float*)d_in[4];
    const float* e2_w      = (const float*)d_in[5];
    const float* e2_g      = (const float*)d_in[6];
    const float* e2_b      = (const float*)d_in[7];
    const float* cal1_w    = (const float*)d_in[8];
    const float* cal1_g    = (const float*)d_in[9];
    const float* cal1_b    = (const float*)d_in[10];
    const float* cal2_w    = (const float*)d_in[11];
    const float* cal2_bias = (const float*)d_in[12];
    const float* exp1_w    = (const float*)d_in[13];
    const float* exp1_g    = (const float*)d_in[14];
    const float* exp1_b    = (const float*)d_in[15];
    const float* exp2_w    = (const float*)d_in[16];
    const float* exp2_g    = (const float*)d_in[17];
    const float* exp2_b    = (const float*)d_in[18];
    const float* red_w     = (const float*)d_in[19];
    const float* red_g     = (const float*)d_in[20];
    const float* red_b     = (const float*)d_in[21];
    const float* sc1_w     = (const float*)d_in[22];
    const float* sc1_b     = (const float*)d_in[23];
    const float* sc2_w     = (const float*)d_in[24];
    const float* sc2_b     = (const float*)d_in[25];
    const float* n1_g      = (const float*)d_in[26];
    const float* n1_b      = (const float*)d_in[27];
    const float* n2_g      = (const float*)d_in[28];
    const float* n2_b      = (const float*)d_in[29];

    float *dx, *dbig, *dcat, *dgt, *dx1, *dh, *dwt;
    cudaGetSymbolAddress((void**)&dx,   d_x_);
    cudaGetSymbolAddress((void**)&dbig, d_big_);
    cudaGetSymbolAddress((void**)&dcat, d_cat_);
    cudaGetSymbolAddress((void**)&dgt,  d_gt_);
    cudaGetSymbolAddress((void**)&dx1,  d_x1_);
    cudaGetSymbolAddress((void**)&dh,   d_h_);
    cudaGetSymbolAddress((void**)&dwt,  d_wt_);

    prep_pack<<<(WP_EXP2 + 255) / 256, 256>>>(e1_w, e2_w, cal1_w, cal2_w, exp1_w,
                                              exp2_w, red_w, sc1_w, sc2_w, 0);
    prep_pack<<<(WP_TOT - WP_EXP2 + 255) / 256, 256>>>(e1_w, e2_w, cal1_w, cal2_w, exp1_w,
                                                       exp2_w, red_w, sc1_w, sc2_w, 1);
    knn_kernel<<<512, 64>>>(xyz, feats);

    // EdgeConv1 fused (GEMM + gather-max) -> d_cat[0:64)
    gemm_k<7, 128><<<dim3(512, 1, 1), 256>>>(dx, 4096, 64, dwt + WP_WS1, 64, 128,
                                             dcat, 12288, 64, 0,
                                             e1_g, e1_b, nullptr, nullptr, nullptr);
    // EdgeConv2 fused -> d_cat[64:192)
    gemm_k<7, 128><<<dim3(512, 1, 2), 256>>>(dcat, 12288, 64, dwt + WP_WS2, 64, 256,
                                             dcat, 12288, 64, 64,
                                             e2_g, e2_b, nullptr, nullptr, nullptr);

    // fused calib (cal1 + cal2 + sigmoid gate, in-place on d_cat)
    calib_kernel<<<512, 256>>>(dcat, cal1_g, cal1_b, cal2_bias);

    // exp1: relu(bn(exp1@x))
    gemm_k<1, 128><<<dim3(512, 1, 2), 256>>>(dcat, 12288, 64, dwt + WP_EXP1, 192, 256,
                                             dbig, 16384, 64, 0,
                                             exp1_g, exp1_b, nullptr, nullptr, nullptr);
    // exp2 + max over 64 points -> pooled [b][512][256]
    gemm_k<3, 128><<<dim3(512, 1, 4), 256>>>(dbig, 16384, 64, dwt + WP_EXP2, 256, 512,
                                             dgt, 0, 0, 0,
                                             exp2_g, exp2_b, nullptr, nullptr, nullptr);

    // red: x1 = bn1( 2 * relu(bn(red@pooled)) )
    gemm_k<4, 64><<<dim3(2, 4, 4), 256>>>(dgt, 131072, 256, dwt + WP_RED, 512, 256,
                                          dx1, 65536, 256, 0,
                                          red_g, red_b, n1_g, n1_b, nullptr);
    // sc1: h = relu(sc1@x1 + b)
    gemm_k<5, 64><<<dim3(2, 4, 4), 256>>>(dx1, 65536, 256, dwt + WP_SC1, 256, 256,
                                          dh, 65536, 256, 0,
                                          sc1_b, nullptr, nullptr, nullptr, nullptr);
    // sc2 + residual + bn2 -> final output (B, 256, 256)
    gemm_k<6, 64><<<dim3(2, 4, 4), 256>>>(dh, 65536, 256, dwt + WP_SC2, 256, 256,
                                          (float*)d_out, 65536, 256, 0,
                                          sc2_b, n2_g, n2_b, nullptr, dx1);
}

// round 13
// speedup vs baseline: 1.6064x; 1.6064x over previous
#include <cuda_runtime.h>
#include <cstdint>
#include <cfloat>
#include <math.h>

// ---------------------------------------------------------------------------
// Problem constants
//   B=2, M=256 -> 512 groups, 64 points/group, KNN=16, CIN=64 (3 xyz + 61 feat)
//   MLPS=[64,128], SUMM=192, CALIB=64, EXP=[256,512], OUT=256
// ---------------------------------------------------------------------------

// Scratch (static device arrays; no runtime allocation)
__device__ float d_x_[512 * 64 * 64];      // input panel  [g][c(64)][n(64)]
__device__ int   d_idx_[512 * 64 * 16];    // knn indices  [g][n][k]
__device__ float d_big_[512 * 256 * 64];   // exp1 out
__device__ float d_cat_[512 * 192 * 64];   // concat features [g][c(192)][n]
__device__ float d_gt_[2 * 512 * 256];     // pooled vector, [b][c(512)][m(256)]
__device__ float d_x1_[2 * 256 * 256];     // after red+bn1
__device__ float d_h_[2 * 256 * 256];      // sc1 out

// All weights, transposed to [c][o] (plain float — o-pairs are natural f32x2).
//   ws1   @0       64c x 128o  ([W1(64) ; W2-W1(64)])
//   ws2   @8192    64c x 256o  per-block interleave: o'=half*128+r,
//                              r<64 -> W1 row half*64+r ; r>=64 -> (W2-W1) row half*64+(r-64)
//   cal1  @24576  192c x  64o
//   cal2  @36864   64c x 192o
//   exp1  @49152  192c x 256o
//   exp2  @98304  256c x 512o
//   red   @229376 512c x 256o
//   sc1   @360448 256c x 256o
//   sc2   @425984 256c x 256o
#define WP_WS1  0
#define WP_WS2  8192
#define WP_CAL1 24576
#define WP_CAL2 36864
#define WP_EXP1 49152
#define WP_EXP2 98304
#define WP_RED  229376
#define WP_SC1  360448
#define WP_SC2  425984
#define WP_TOT  491520
__device__ float d_wt_[WP_TOT];

// ---------------------------------------------------------------------------
// f32x2 packed-FMA + cp.async helpers
// ---------------------------------------------------------------------------
__device__ __forceinline__ unsigned long long pack2(float v) {
    unsigned long long r;
    asm("mov.b64 %0, {%1, %1};" : "=l"(r) : "r"(__float_as_uint(v)));
    return r;
}
__device__ __forceinline__ void ffma2(unsigned long long& d,
                                      unsigned long long a, unsigned long long b) {
    asm("fma.rn.f32x2 %0, %1, %2, %0;" : "+l"(d) : "l"(a), "l"(b));
}
__device__ __forceinline__ float lo2(unsigned long long v) { return __uint_as_float((unsigned)v); }
__device__ __forceinline__ float hi2(unsigned long long v) { return __uint_as_float((unsigned)(v >> 32)); }

__device__ __forceinline__ void cp16(unsigned int dst, const void* src) {
    asm volatile("cp.async.cg.shared.global [%0], [%1], 16;" :: "r"(dst), "l"(src));
}
__device__ __forceinline__ void cp_commit() { asm volatile("cp.async.commit_group;"); }
template<int N> __device__ __forceinline__ void cp_wait() {
    asm volatile("cp.async.wait_group %0;" :: "n"(N));
}

// ---------------------------------------------------------------------------
// K0 (x2 launches): transpose ALL weights into d_wt_ ([c][o], plain float).
// ---------------------------------------------------------------------------
__global__ void prep_pack(const float* __restrict__ e1w, const float* __restrict__ e2w,
                          const float* __restrict__ cal1w, const float* __restrict__ cal2w,
                          const float* __restrict__ exp1w, const float* __restrict__ exp2w,
                          const float* __restrict__ redw, const float* __restrict__ sc1w,
                          const float* __restrict__ sc2w, int part) {
    int i = blockIdx.x * blockDim.x + threadIdx.x + (part ? WP_EXP2 : 0);
    if (part == 0) {
        if (i >= WP_EXP2) return;
    } else {
        if (i >= WP_TOT) return;
    }
    float v;
    if (i < WP_WS2) {                 // ws1: O=128, C=64
        int l = i - WP_WS1, c = l >> 7, o = l & 127;
        v = (o < 64) ? e1w[o * 128 + c]
                     : e1w[(o - 64) * 128 + 64 + c] - e1w[(o - 64) * 128 + c];
    } else if (i < WP_CAL1) {         // ws2: O=256 (per-block [U;T] interleave)
        int l = i - WP_WS2, c = l >> 8, op = l & 255;
        int half = op >> 7, r = op & 127;
        int row = half * 64 + (r & 63);
        v = (r < 64) ? e2w[row * 128 + c]
                     : e2w[row * 128 + 64 + c] - e2w[row * 128 + c];
    } else if (i < WP_CAL2) {         // cal1: O=64, C=192
        int l = i - WP_CAL1, c = l >> 6, o = l & 63;
        v = cal1w[o * 192 + c];
    } else if (i < WP_EXP1) {         // cal2: O=192, C=64
        int l = i - WP_CAL2, c = l / 192, o = l % 192;
        v = cal2w[o * 64 + c];
    } else if (i < WP_EXP2) {         // exp1: O=256, C=192
        int l = i - WP_EXP1, c = l >> 8, o = l & 255;
        v = exp1w[o * 192 + c];
    } else if (i < WP_RED) {          // exp2: O=512, C=256
        int l = i - WP_EXP2, c = l >> 9, o = l & 511;
        v = exp2w[o * 256 + c];
    } else if (i < WP_SC1) {          // red: O=256, C=512
        int l = i - WP_RED, c = l >> 8, o = l & 255;
        v = redw[o * 512 + c];
    } else if (i < WP_SC2) {          // sc1: O=256, C=256
        int l = i - WP_SC1, c = l >> 8, o = l & 255;
        v = sc1w[o * 256 + c];
    } else {                          // sc2: O=256, C=256
        int l = i - WP_SC2, c = l >> 8, o = l & 255;
        v = sc2w[o * 256 + c];
    }
    d_wt_[i] = v;
}

// ---------------------------------------------------------------------------
// K1: build input panel d_x (xyz+feats transposed) + 16-NN per point.
// ---------------------------------------------------------------------------
__global__ void knn_kernel(const float* __restrict__ xyz, const float* __restrict__ feats) {
    int g = blockIdx.x, t = threadIdx.x;
    __shared__ float px[64], py[64], pz[64], xx[64];
    __shared__ float sbuf[64 * 65];

    int b3 = (g * 64 + t) * 3;
    float ax = xyz[b3 + 0], ay = xyz[b3 + 1], az = xyz[b3 + 2];
    px[t] = ax; py[t] = ay; pz[t] = az;
    xx[t] = ax * ax + ay * ay + az * az;

    float* xg = d_x_ + (size_t)g * 4096;
    xg[0 * 64 + t] = ax; xg[1 * 64 + t] = ay; xg[2 * 64 + t] = az;

    const float* fg = feats + (size_t)g * 64 * 61;
    for (int i = 0; i < 61; i++) sbuf[i * 64 + t] = fg[i * 64 + t];
    __syncthreads();
    for (int c = 0; c < 61; c++) xg[(3 + c) * 64 + t] = sbuf[t * 61 + c];
    __syncthreads();

    float* row = &sbuf[t * 65];
    float xn = xx[t];
    for (int m = 0; m < 64; m++)
        row[m] = 2.0f * (ax * px[m] + ay * py[m] + az * pz[m]) - xn - xx[m];

    // top-16 by selection (only the SET matters; max-over-k is order-invariant)
    int* ig = d_idx_ + (g * 64 + t) * 16;
    for (int k = 0; k < 16; k++) {
        float best = -FLT_MAX; int bi = 0;
        for (int m = 0; m < 64; m++) {
            float v = row[m];
            if (v > best) { best = v; bi = m; }
        }
        ig[k] = bi;
        row[bi] = -FLT_MAX;
    }
}

// ---------------------------------------------------------------------------
// K_calib: fused cal1 -> bn/relu -> cal2 -> sigmoid gate (in-place on d_cat).
// One block per group. GEMM1: 64o x 64n, CIN=192 (pipelined).
// GEMM2: 3 passes of 64o, CIN=64, X = Cs resident in smem.
// ---------------------------------------------------------------------------
__global__ void __launch_bounds__(256)
calib_kernel(float* __restrict__ cat,
             const float* __restrict__ c1g, const float* __restrict__ c1b,
             const float* __restrict__ c2bias) {
    __shared__ __align__(16) float XsP[3 * 16 * 64];
    __shared__ __align__(16) float WsP[3 * 16 * 64];
    __shared__ __align__(16) float Cs[64 * 64];

    const int g = blockIdx.x, t = threadIdx.x;
    const int tn = t & 15, to = t >> 4;
    const int cr = t >> 4, wc4 = (t & 15) << 2;
    const unsigned int xs_s = (unsigned int)__cvta_generic_to_shared(XsP);
    const unsigned int ws_s = (unsigned int)__cvta_generic_to_shared(WsP);
    const float* Xg = cat + (size_t)g * 12288;
    const float* W1 = d_wt_ + WP_CAL1;   // [c(192)][64]
    const float* W2 = d_wt_ + WP_CAL2;   // [c(64)][192]
    const float INVS = rsqrtf(1.0f + 1e-5f);

    // ---- GEMM1: CIN=192 -> 12 chunks ----
    unsigned long long a1[2][4];
    #pragma unroll
    for (int p = 0; p < 2; p++)
        #pragma unroll
        for (int j = 0; j < 4; j++) a1[p][j] = 0ull;

    auto pf1 = [&](int cb, int st) {
        if (cb < 12) {
            int c0 = cb << 4;
            cp16(xs_s + (unsigned int)(st * 1024 + cr * 64 + wc4) * 4,
                 Xg + (size_t)(c0 + cr) * 64 + wc4);
            cp16(ws_s + (unsigned int)(st * 1024 + cr * 64 + wc4) * 4,
                 W1 + (size_t)(c0 + cr) * 64 + wc4);
        }
        cp_commit();
    };
    pf1(0, 0); pf1(1, 1);
    int st = 0;
    for (int cb = 0; cb < 12; cb++) {
        cp_wait<1>();
        __syncthreads();
        pf1(cb + 2, (st + 2) % 3);
        #pragma unroll
        for (int c = 0; c < 16; c++) {
            float4 xv = *reinterpret_cast<const float4*>(&XsP[(st * 16 + c) * 64 + (tn << 2)]);
            unsigned long long xd0 = pack2(xv.x), xd1 = pack2(xv.y);
            unsigned long long xd2 = pack2(xv.z), xd3 = pack2(xv.w);
            ulonglong2 w = *reinterpret_cast<const ulonglong2*>(&WsP[(st * 16 + c) * 64 + (to << 2)]);
            ffma2(a1[0][0], w.x, xd0); ffma2(a1[0][1], w.x, xd1);
            ffma2(a1[0][2], w.x, xd2); ffma2(a1[0][3], w.x, xd3);
            ffma2(a1[1][0], w.y, xd0); ffma2(a1[1][1], w.y, xd1);
            ffma2(a1[1][2], w.y, xd2); ffma2(a1[1][3], w.y, xd3);
        }
        st = (st + 1) % 3;
    }
    // bn + relu -> Cs
    {
        float a[4][4];
        #pragma unroll
        for (int p = 0; p < 2; p++)
            #pragma unroll
            for (int j = 0; j < 4; j++) {
                a[2 * p][j]     = lo2(a1[p][j]);
                a[2 * p + 1][j] = hi2(a1[p][j]);
            }
        #pragma unroll
        for (int i = 0; i < 4; i++) {
            int o = (to << 2) + i;
            float s = c1g[o] * INVS, b = c1b[o];
            float4 v;
            v.x = fmaxf(fmaf(a[i][0], s, b), 0.0f);
            v.y = fmaxf(fmaf(a[i][1], s, b), 0.0f);
            v.z = fmaxf(fmaf(a[i][2], s, b), 0.0f);
            v.w = fmaxf(fmaf(a[i][3], s, b), 0.0f);
            *reinterpret_cast<float4*>(&Cs[o * 64 + (tn << 2)]) = v;
        }
    }
    __syncthreads();   // Cs visible; pipeline buffers free for GEMM2

    // ---- GEMM2 + gate: 12 chunks (3 passes x 4), CIN=64, X = Cs ----
    auto pf2 = [&](int q, int stg) {
        if (q < 12) {
            int pass = q >> 2, c0 = (q & 3) << 4, ooff = pass << 6;
            cp16(ws_s + (unsigned int)(stg * 1024 + cr * 64 + wc4) * 4,
                 W2 + (size_t)(c0 + cr) * 192 + ooff + wc4);
        }
        cp_commit();
    };
    pf2(0, 0); pf2(1, 1);
    st = 0;
    for (int pass = 0; pass < 3; pass++) {
        unsigned long long a2[2][4];
        #pragma unroll
        for (int p = 0; p < 2; p++)
            #pragma unroll
            for (int j = 0; j < 4; j++) a2[p][j] = 0ull;
        for (int cq = 0; cq < 4; cq++) {
            int q = pass * 4 + cq;
            cp_wait<1>();
            __syncthreads();
            pf2(q + 2, (st + 2) % 3);
            #pragma unroll
            for (int c = 0; c < 16; c++) {
                float4 xv = *reinterpret_cast<const float4*>(&Cs[((cq << 4) + c) * 64 + (tn << 2)]);
                unsigned long long xd0 = pack2(xv.x), xd1 = pack2(xv.y);
                unsigned long long xd2 = pack2(xv.z), xd3 = pack2(xv.w);
                ulonglong2 w = *reinterpret_cast<const ulonglong2*>(&WsP[(st * 16 + c) * 64 + (to << 2)]);
                ffma2(a2[0][0], w.x, xd0); ffma2(a2[0][1], w.x, xd1);
                ffma2(a2[0][2], w.x, xd2); ffma2(a2[0][3], w.x, xd3);
                ffma2(a2[1][0], w.y, xd0); ffma2(a2[1][1], w.y, xd1);
                ffma2(a2[1][2], w.y, xd2); ffma2(a2[1][3], w.y, xd3);
            }
            st = (st + 1) % 3;
        }
        // gate epilogue for this 64-output pass
        float a[4][4];
        #pragma unroll
        for (int p = 0; p < 2; p++)
            #pragma unroll
            for (int j = 0; j < 4; j++) {
                a[2 * p][j]     = lo2(a2[p][j]);
                a[2 * p + 1][j] = hi2(a2[p][j]);
            }
        int ooff = pass << 6;
        #pragma unroll
        for (int i = 0; i < 4; i++) {
            int o = ooff + (to << 2) + i;
            float bb = c2bias[o];
            size_t ob = (size_t)g * 12288 + (size_t)o * 64 + (tn << 2);
            float4 xin = *reinterpret_cast<const float4*>(&cat[ob]);
            float4 r;
            r.x = xin.x / (1.0f + expf(-(a[i][0] + bb)));
            r.y = xin.y / (1.0f + expf(-(a[i][1] + bb)));
            r.z = xin.z / (1.0f + expf(-(a[i][2] + bb)));
            r.w = xin.w / (1.0f + expf(-(a[i][3] + bb)));
            *reinterpret_cast<float4*>(&cat[ob]) = r;
        }
    }
}

// ---------------------------------------------------------------------------
// Fused GEMM, o-paired FFMA2:  out(OT o x 64col) = epi( W @ X )
// W pre-transposed [c][wO] plain float: consecutive o's ARE the f32x2 pair.
// 3-stage cp.async pipeline, one sync per 16-channel chunk.
// Epilogues: 0 raw | 1 relu(bn) | 3 relu(bn)+max-over-col
//            4 red: relu(bn)*2->bn1 | 5 bias+relu | 6 final bn2(x1+acc+b)
//            7 EdgeConv fused gather-max (OT=128: rows 0..63=U, 64..127=T)
// ---------------------------------------------------------------------------
template<int EPI, int OT>
__global__ void __launch_bounds__(256)
gemm_k(const float* __restrict__ X, int imgStride, int cpi,
       const float* __restrict__ Wt, int CIN, int wO,
       float* out, int outImgStride, int outCpi, int chanOff,
       const float* p0, const float* p1, const float* p2, const float* p3,
       const float* aux) {
    constexpr int OPT = OT / 16;       // outputs per thread (8 or 4)
    constexpr int PAIRS = OPT / 2;     // f32x2 pairs per thread (4 or 2)
    constexpr int PIPE_F = 3 * 16 * 64 + 3 * 16 * OT;
    constexpr int EPI7_F = (EPI == 7) ? (4096 + 4096 + 64 * 17) : 0;
    constexpr int SM_F = PIPE_F > EPI7_F ? PIPE_F : EPI7_F;
    __shared__ __align__(16) float smbuf[SM_F];
    float* XsP = smbuf;                 // [(st*16+c)*64 + col]
    float* WsP = smbuf + 3 * 16 * 64;   // [(st*16+c)*OT + o]

    const int g = blockIdx.x;
    const int colBase = blockIdx.y << 6;
    const int oBase = blockIdx.z * OT;
    const int t = threadIdx.x;
    const int tn = t & 15, to = t >> 4;

    const float* Xg = X + (size_t)g * imgStride + colBase;

    const int cr = t >> 4;
    const int xc = (t & 15) << 2;
    const unsigned int xs_s = (unsigned int)__cvta_generic_to_shared(XsP);
    const unsigned int ws_s = (unsigned int)__cvta_generic_to_shared(WsP);
    const int nch = CIN >> 4;

    unsigned long long acc2[PAIRS][4];
    #pragma unroll
    for (int p = 0; p < PAIRS; p++)
        #pragma unroll
        for (int j = 0; j < 4; j++) acc2[p][j] = 0ull;

    auto prefetch = [&](int cb, int stg) {
        if (cb < nch) {
            const int c0 = cb << 4;
            cp16(xs_s + (unsigned int)(stg * 1024 + cr * 64 + xc) * 4,
                 Xg + (size_t)(c0 + cr) * cpi + xc);
            const float* wrow = Wt + (size_t)(c0 + cr) * wO + oBase;
            if constexpr (OT == 128) {
                const int wc = (t & 15) << 3;
                cp16(ws_s + (unsigned int)(stg * 16 * OT + cr * OT + wc) * 4, wrow + wc);
                cp16(ws_s + (unsigned int)(stg * 16 * OT + cr * OT + wc + 4) * 4, wrow + wc + 4);
            } else {
                const int wc = (t & 15) << 2;
                cp16(ws_s + (unsigned int)(stg * 16 * OT + cr * OT + wc) * 4, wrow + wc);
            }
        }
        cp_commit();
    };

    prefetch(0, 0);
    prefetch(1, 1);

    int st = 0, stn = 2;
    for (int cb = 0; cb < nch; cb++) {
        cp_wait<1>();
        __syncthreads();
        prefetch(cb + 2, stn);
        #pragma unroll
        for (int c = 0; c < 16; c++) {
            float4 xv = *reinterpret_cast<const float4*>(&XsP[(st * 16 + c) * 64 + (tn << 2)]);
            unsigned long long xd0 = pack2(xv.x), xd1 = pack2(xv.y);
            unsigned long long xd2 = pack2(xv.z), xd3 = pack2(xv.w);
            const ulonglong2* wr =
                reinterpret_cast<const ulonglong2*>(&WsP[(st * 16 + c) * OT + to * OPT]);
            unsigned long long wp[PAIRS];
            {
                ulonglong2 w0 = wr[0];
                wp[0] = w0.x; wp[1] = w0.y;
                if constexpr (PAIRS == 4) {
                    ulonglong2 w1 = wr[1];
                    wp[2] = w1.x; wp[3] = w1.y;
                }
            }
            #pragma unroll
            for (int p = 0; p < PAIRS; p++) {
                ffma2(acc2[p][0], wp[p], xd0);
                ffma2(acc2[p][1], wp[p], xd1);
                ffma2(acc2[p][2], wp[p], xd2);
                ffma2(acc2[p][3], wp[p], xd3);
            }
        }
        st = (st == 2) ? 0 : st + 1;
        stn = (stn == 2) ? 0 : stn + 1;
    }

    float acc[OPT][4];
    #pragma unroll
    for (int p = 0; p < PAIRS; p++)
        #pragma unroll
        for (int j = 0; j < 4; j++) {
            acc[2 * p][j]     = lo2(acc2[p][j]);
            acc[2 * p + 1][j] = hi2(acc2[p][j]);
        }
    const float INVS = rsqrtf(1.0f + 1e-5f);

    if constexpr (EPI == 7) {
        float* Us = smbuf;
        float* Ts = smbuf + 4096;
        int*   sidx = (int*)(smbuf + 8192);
        __syncthreads();
        #pragma unroll
        for (int i = 0; i < OPT; i++) {
            int r = to * OPT + i;
            float* dst = (r < 64) ? &Us[r * 64] : &Ts[(r - 64) * 64];
            #pragma unroll
            for (int j = 0; j < 4; j++) dst[(tn << 2) + j] = acc[i][j];
        }
        const int* idg = d_idx_ + g * 1024;
        for (int i = t; i < 1024; i += 256)
            sidx[(i >> 4) * 17 + (i & 15)] = idg[i];
        __syncthreads();

        const int bnoff = blockIdx.z << 6;
        float* outg = out + (size_t)g * outImgStride + (size_t)(chanOff + bnoff) * outCpi;
        for (int item = t; item < 4096; item += 256) {
            int o = item >> 6, n = item & 63;
            float T = Ts[o * 64 + n];
            float s = p0[bnoff + o] * INVS, b = p1[bnoff + o];
            const float* Uo = &Us[o * 64];
            const int*   ni = &sidx[n * 17];
            float m = -FLT_MAX;
            #pragma unroll
            for (int k = 0; k < 16; k++) {
                float v = fmaf(Uo[ni[k]] + T, s, b);
                m = fmaxf(m, fmaxf(v, 0.0f));
            }
            outg[o * (size_t)outCpi + n] = m;
        }
    } else if constexpr (EPI == 3) {
        float* red = smbuf;
        __syncthreads();
        #pragma unroll
        for (int i = 0; i < OPT; i++) {
            int o = oBase + to * OPT + i;
            float s = p0[o] * INVS, b = p1[o];
            float m = -FLT_MAX;
            #pragma unroll
            for (int j = 0; j < 4; j++)
                m = fmaxf(m, fmaxf(fmaf(acc[i][j], s, b), 0.0f));
            red[(to * OPT + i) * 17 + tn] = m;
        }
        __syncthreads();
        if (t < OT) {
            float m = red[t * 17];
            #pragma unroll
            for (int q = 1; q < 16; q++) m = fmaxf(m, red[t * 17 + q]);
            int bb = g >> 8, mm = g & 255;
            out[((size_t)bb * 512 + oBase + t) * 256 + mm] = m;
        }
    } else {
        #pragma unroll
        for (int i = 0; i < OPT; i++) {
            int o = oBase + to * OPT + i;
            size_t ob = (size_t)g * outImgStride + (size_t)(chanOff + o) * outCpi
                      + colBase + (tn << 2);
            if constexpr (EPI == 0) {
                #pragma unroll
                for (int j = 0; j < 4; j++) out[ob + j] = acc[i][j];
            } else if constexpr (EPI == 1) {
                float s = p0[o] * INVS, b = p1[o];
                #pragma unroll
                for (int j = 0; j < 4; j++)
                    out[ob + j] = fmaxf(fmaf(acc[i][j], s, b), 0.0f);
            } else if constexpr (EPI == 4) {
                float sr = p0[o] * INVS, br = p1[o];
                float s1 = p2[o] * INVS, b1 = p3[o];
                #pragma unroll
                for (int j = 0; j < 4; j++) {
                    float r = fmaxf(fmaf(acc[i][j], sr, br), 0.0f);
                    out[ob + j] = fmaf(2.0f * r, s1, b1);
                }
            } else if constexpr (EPI == 5) {
                float bb = p0[o];
                #pragma unroll
                for (int j = 0; j < 4; j++)
                    out[ob + j] = fmaxf(acc[i][j] + bb, 0.0f);
            } else if constexpr (EPI == 6) {
                float bb = p0[o], s2 = p1[o] * INVS, b2 = p2[o];
                #pragma unroll
                for (int j = 0; j < 4; j++) {
                    float v = acc[i][j] + bb + aux[ob + j];
                    out[ob + j] = fmaf(v, s2, b2);
                }
            }
        }
    }
}

// ---------------------------------------------------------------------------
extern "C" void kernel_launch(void* const* d_in, const int* in_sizes, int n_in,
                              void* d_out, int out_size) {
    const float* xyz       = (const float*)d_in[0];
    const float* feats     = (const float*)d_in[1];
    const float* e1_w      = (const float*)d_in[2];
    const float* e1_g      = (const float*)d_in[3];
    const float* e1_b      = (const float*)d_in[4];
    const float* e2_w      = (const float*)d_in[5];
    const float* e2_g      = (const float*)d_in[6];
    const float* e2_b      = (const float*)d_in[7];
    const float* cal1_w    = (const float*)d_in[8];
    const float* cal1_g    = (const float*)d_in[9];
    const float* cal1_b    = (const float*)d_in[10];
    const float* cal2_w    = (const float*)d_in[11];
    const float* cal2_bias = (const float*)d_in[12];
    const float* exp1_w    = (const float*)d_in[13];
    const float* exp1_g    = (const float*)d_in[14];
    const float* exp1_b    = (const float*)d_in[15];
    const float* exp2_w    = (const float*)d_in[16];
    const float* exp2_g    = (const float*)d_in[17];
    const float* exp2_b    = (const float*)d_in[18];
    const float* red_w     = (const float*)d_in[19];
    const float* red_g     = (const float*)d_in[20];
    const float* red_b     = (const float*)d_in[21];
    const float* sc1_w     = (const float*)d_in[22];
    const float* sc1_b     = (const float*)d_in[23];
    const float* sc2_w     = (const float*)d_in[24];
    const float* sc2_b     = (const float*)d_in[25];
    const float* n1_g      = (const float*)d_in[26];
    const float* n1_b      = (const float*)d_in[27];
    const float* n2_g      = (const float*)d_in[28];
    const float* n2_b      = (const float*)d_in[29];

    float *dx, *dbig, *dcat, *dgt, *dx1, *dh, *dwt;
    cudaGetSymbolAddress((void**)&dx,   d_x_);
    cudaGetSymbolAddress((void**)&dbig, d_big_);
    cudaGetSymbolAddress((void**)&dcat, d_cat_);
    cudaGetSymbolAddress((void**)&dgt,  d_gt_);
    cudaGetSymbolAddress((void**)&dx1,  d_x1_);
    cudaGetSymbolAddress((void**)&dh,   d_h_);
    cudaGetSymbolAddress((void**)&dwt,  d_wt_);

    prep_pack<<<(WP_EXP2 + 255) / 256, 256>>>(e1_w, e2_w, cal1_w, cal2_w, exp1_w,
                                              exp2_w, red_w, sc1_w, sc2_w, 0);
    prep_pack<<<(WP_TOT - WP_EXP2 + 255) / 256, 256>>>(e1_w, e2_w, cal1_w, cal2_w, exp1_w,
                                                       exp2_w, red_w, sc1_w, sc2_w, 1);
    knn_kernel<<<512, 64>>>(xyz, feats);

    // EdgeConv1 fused (GEMM + gather-max) -> d_cat[0:64)
    gemm_k<7, 128><<<dim3(512, 1, 1), 256>>>(dx, 4096, 64, dwt + WP_WS1, 64, 128,
                                             dcat, 12288, 64, 0,
                                             e1_g, e1_b, nullptr, nullptr, nullptr);
    // EdgeConv2 fused -> d_cat[64:192)
    gemm_k<7, 128><<<dim3(512, 1, 2), 256>>>(dcat, 12288, 64, dwt + WP_WS2, 64, 256,
                                             dcat, 12288, 64, 64,
                                             e2_g, e2_b, nullptr, nullptr, nullptr);

    // fused calib (cal1 + cal2 + sigmoid gate, in-place on d_cat)
    calib_kernel<<<512, 256>>>(dcat, cal1_g, cal1_b, cal2_bias);

    // exp1: relu(bn(exp1@x))
    gemm_k<1, 128><<<dim3(512, 1, 2), 256>>>(dcat, 12288, 64, dwt + WP_EXP1, 192, 256,
                                             dbig, 16384, 64, 0,
                                             exp1_g, exp1_b, nullptr, nullptr, nullptr);
    // exp2 + max over 64 points -> pooled [b][512][256]
    gemm_k<3, 128><<<dim3(512, 1, 4), 256>>>(dbig, 16384, 64, dwt + WP_EXP2, 256, 512,
                                             dgt, 0, 0, 0,
                                             exp2_g, exp2_b, nullptr, nullptr, nullptr);

    // red: x1 = bn1( 2 * relu(bn(red@pooled)) )
    gemm_k<4, 64><<<dim3(2, 4, 4), 256>>>(dgt, 131072, 256, dwt + WP_RED, 512, 256,
                                          dx1, 65536, 256, 0,
                                          red_g, red_b, n1_g, n1_b, nullptr);
    // sc1: h = relu(sc1@x1 + b)
    gemm_k<5, 64><<<dim3(2, 4, 4), 256>>>(dx1, 65536, 256, dwt + WP_SC1, 256, 256,
                                          dh, 65536, 256, 0,
                                          sc1_b, nullptr, nullptr, nullptr, nullptr);
    // sc2 + residual + bn2 -> final output (B, 256, 256)
    gemm_k<6, 64><<<dim3(2, 4, 4), 256>>>(dh, 65536, 256, dwt + WP_SC2, 256, 256,
                                          (float*)d_out, 65536, 256, 0,
                                          sc2_b, n2_g, n2_b, nullptr, dx1);
}

// round 15
// speedup vs baseline: 1.6992x; 1.0578x over previous
#include <cuda_runtime.h>
#include <cstdint>
#include <cfloat>
#include <math.h>

// ---------------------------------------------------------------------------
// Problem constants
//   B=2, M=256 -> 512 groups, 64 points/group, KNN=16, CIN=64 (3 xyz + 61 feat)
//   MLPS=[64,128], SUMM=192, CALIB=64, EXP=[256,512], OUT=256
// ---------------------------------------------------------------------------

// Scratch (static device arrays; no runtime allocation)
__device__ float d_x_[512 * 64 * 64];      // input panel  [g][c(64)][n(64)]
__device__ int   d_idx_[512 * 64 * 16];    // knn indices  [g][n][k]
__device__ float d_big_[512 * 256 * 64];   // exp1 out
__device__ float d_cat_[512 * 192 * 64];   // concat features [g][c(192)][n]
__device__ float d_gt_[2 * 512 * 256];     // pooled vector, [b][c(512)][m(256)]
__device__ float d_x1_[2 * 256 * 256];     // after red+bn1
__device__ float d_h_[2 * 256 * 256];      // sc1 out

// All weights, transposed to [c][o] (plain float — o-pairs are natural f32x2).
#define WP_WS1  0
#define WP_WS2  8192
#define WP_CAL1 24576
#define WP_CAL2 36864
#define WP_EXP1 49152
#define WP_EXP2 98304
#define WP_RED  229376
#define WP_SC1  360448
#define WP_SC2  425984
#define WP_TOT  491520
__device__ float d_wt_[WP_TOT];

// ---------------------------------------------------------------------------
// f32x2 packed-FMA + cp.async helpers
// ---------------------------------------------------------------------------
__device__ __forceinline__ unsigned long long pack2(float v) {
    unsigned long long r;
    asm("mov.b64 %0, {%1, %1};" : "=l"(r) : "r"(__float_as_uint(v)));
    return r;
}
__device__ __forceinline__ void ffma2(unsigned long long& d,
                                      unsigned long long a, unsigned long long b) {
    asm("fma.rn.f32x2 %0, %1, %2, %0;" : "+l"(d) : "l"(a), "l"(b));
}
__device__ __forceinline__ float lo2(unsigned long long v) { return __uint_as_float((unsigned)v); }
__device__ __forceinline__ float hi2(unsigned long long v) { return __uint_as_float((unsigned)(v >> 32)); }

__device__ __forceinline__ void cp16(unsigned int dst, const void* src) {
    asm volatile("cp.async.cg.shared.global [%0], [%1], 16;" :: "r"(dst), "l"(src));
}
__device__ __forceinline__ void cp_commit() { asm volatile("cp.async.commit_group;"); }
template<int N> __device__ __forceinline__ void cp_wait() {
    asm volatile("cp.async.wait_group %0;" :: "n"(N));
}

// ---------------------------------------------------------------------------
// K0 (x2 launches): transpose ALL weights into d_wt_ ([c][o], plain float).
// ---------------------------------------------------------------------------
__global__ void prep_pack(const float* __restrict__ e1w, const float* __restrict__ e2w,
                          const float* __restrict__ cal1w, const float* __restrict__ cal2w,
                          const float* __restrict__ exp1w, const float* __restrict__ exp2w,
                          const float* __restrict__ redw, const float* __restrict__ sc1w,
                          const float* __restrict__ sc2w, int part) {
    int i = blockIdx.x * blockDim.x + threadIdx.x + (part ? WP_EXP2 : 0);
    if (part == 0) {
        if (i >= WP_EXP2) return;
    } else {
        if (i >= WP_TOT) return;
    }
    float v;
    if (i < WP_WS2) {                 // ws1: O=128, C=64
        int l = i - WP_WS1, c = l >> 7, o = l & 127;
        v = (o < 64) ? e1w[o * 128 + c]
                     : e1w[(o - 64) * 128 + 64 + c] - e1w[(o - 64) * 128 + c];
    } else if (i < WP_CAL1) {         // ws2: O=256 (per-block [U;T] interleave)
        int l = i - WP_WS2, c = l >> 8, op = l & 255;
        int half = op >> 7, r = op & 127;
        int row = half * 64 + (r & 63);
        v = (r < 64) ? e2w[row * 128 + c]
                     : e2w[row * 128 + 64 + c] - e2w[row * 128 + c];
    } else if (i < WP_CAL2) {         // cal1: O=64, C=192
        int l = i - WP_CAL1, c = l >> 6, o = l & 63;
        v = cal1w[o * 192 + c];
    } else if (i < WP_EXP1) {         // cal2: O=192, C=64
        int l = i - WP_CAL2, c = l / 192, o = l % 192;
        v = cal2w[o * 64 + c];
    } else if (i < WP_EXP2) {         // exp1: O=256, C=192
        int l = i - WP_EXP1, c = l >> 8, o = l & 255;
        v = exp1w[o * 192 + c];
    } else if (i < WP_RED) {          // exp2: O=512, C=256
        int l = i - WP_EXP2, c = l >> 9, o = l & 511;
        v = exp2w[o * 256 + c];
    } else if (i < WP_SC1) {          // red: O=256, C=512
        int l = i - WP_RED, c = l >> 8, o = l & 255;
        v = redw[o * 512 + c];
    } else if (i < WP_SC2) {          // sc1: O=256, C=256
        int l = i - WP_SC1, c = l >> 8, o = l & 255;
        v = sc1w[o * 256 + c];
    } else {                          // sc2: O=256, C=256
        int l = i - WP_SC2, c = l >> 8, o = l & 255;
        v = sc2w[o * 256 + c];
    }
    d_wt_[i] = v;
}

// ---------------------------------------------------------------------------
// K1: build input panel d_x (xyz+feats transposed) + 16-NN per point.
// ---------------------------------------------------------------------------
__global__ void knn_kernel(const float* __restrict__ xyz, const float* __restrict__ feats) {
    int g = blockIdx.x, t = threadIdx.x;
    __shared__ float px[64], py[64], pz[64], xx[64];
    __shared__ float sbuf[64 * 65];

    int b3 = (g * 64 + t) * 3;
    float ax = xyz[b3 + 0], ay = xyz[b3 + 1], az = xyz[b3 + 2];
    px[t] = ax; py[t] = ay; pz[t] = az;
    xx[t] = ax * ax + ay * ay + az * az;

    float* xg = d_x_ + (size_t)g * 4096;
    xg[0 * 64 + t] = ax; xg[1 * 64 + t] = ay; xg[2 * 64 + t] = az;

    const float* fg = feats + (size_t)g * 64 * 61;
    for (int i = 0; i < 61; i++) sbuf[i * 64 + t] = fg[i * 64 + t];
    __syncthreads();
    for (int c = 0; c < 61; c++) xg[(3 + c) * 64 + t] = sbuf[t * 61 + c];
    __syncthreads();

    float* row = &sbuf[t * 65];
    float xn = xx[t];
    for (int m = 0; m < 64; m++)
        row[m] = 2.0f * (ax * px[m] + ay * py[m] + az * pz[m]) - xn - xx[m];

    // top-16 by selection (only the SET matters; max-over-k is order-invariant)
    int* ig = d_idx_ + (g * 64 + t) * 16;
    for (int k = 0; k < 16; k++) {
        float best = -FLT_MAX; int bi = 0;
        for (int m = 0; m < 64; m++) {
            float v = row[m];
            if (v > best) { best = v; bi = m; }
        }
        ig[k] = bi;
        row[bi] = -FLT_MAX;
    }
}

// ---------------------------------------------------------------------------
// K_calib: fused cal1 -> bn/relu -> cal2 -> sigmoid gate (in-place on d_cat).
// ---------------------------------------------------------------------------
__global__ void __launch_bounds__(256)
calib_kernel(float* __restrict__ cat,
             const float* __restrict__ c1g, const float* __restrict__ c1b,
             const float* __restrict__ c2bias) {
    __shared__ __align__(16) float XsP[3 * 16 * 64];
    __shared__ __align__(16) float WsP[3 * 16 * 64];
    __shared__ __align__(16) float Cs[64 * 64];

    const int g = blockIdx.x, t = threadIdx.x;
    const int tn = t & 15, to = t >> 4;
    const int cr = t >> 4, wc4 = (t & 15) << 2;
    const unsigned int xs_s = (unsigned int)__cvta_generic_to_shared(XsP);
    const unsigned int ws_s = (unsigned int)__cvta_generic_to_shared(WsP);
    const float* Xg = cat + (size_t)g * 12288;
    const float* W1 = d_wt_ + WP_CAL1;
    const float* W2 = d_wt_ + WP_CAL2;
    const float INVS = rsqrtf(1.0f + 1e-5f);

    unsigned long long a1[2][4];
    #pragma unroll
    for (int p = 0; p < 2; p++)
        #pragma unroll
        for (int j = 0; j < 4; j++) a1[p][j] = 0ull;

    auto pf1 = [&](int cb, int st) {
        if (cb < 12) {
            int c0 = cb << 4;
            cp16(xs_s + (unsigned int)(st * 1024 + cr * 64 + wc4) * 4,
                 Xg + (size_t)(c0 + cr) * 64 + wc4);
            cp16(ws_s + (unsigned int)(st * 1024 + cr * 64 + wc4) * 4,
                 W1 + (size_t)(c0 + cr) * 64 + wc4);
        }
        cp_commit();
    };
    pf1(0, 0); pf1(1, 1);
    int st = 0;
    for (int cb = 0; cb < 12; cb++) {
        cp_wait<1>();
        __syncthreads();
        pf1(cb + 2, (st + 2) % 3);
        #pragma unroll
        for (int c = 0; c < 16; c++) {
            float4 xv = *reinterpret_cast<const float4*>(&XsP[(st * 16 + c) * 64 + (tn << 2)]);
            unsigned long long xd0 = pack2(xv.x), xd1 = pack2(xv.y);
            unsigned long long xd2 = pack2(xv.z), xd3 = pack2(xv.w);
            ulonglong2 w = *reinterpret_cast<const ulonglong2*>(&WsP[(st * 16 + c) * 64 + (to << 2)]);
            ffma2(a1[0][0], w.x, xd0); ffma2(a1[0][1], w.x, xd1);
            ffma2(a1[0][2], w.x, xd2); ffma2(a1[0][3], w.x, xd3);
            ffma2(a1[1][0], w.y, xd0); ffma2(a1[1][1], w.y, xd1);
            ffma2(a1[1][2], w.y, xd2); ffma2(a1[1][3], w.y, xd3);
        }
        st = (st + 1) % 3;
    }
    {
        float a[4][4];
        #pragma unroll
        for (int p = 0; p < 2; p++)
            #pragma unroll
            for (int j = 0; j < 4; j++) {
                a[2 * p][j]     = lo2(a1[p][j]);
                a[2 * p + 1][j] = hi2(a1[p][j]);
            }
        #pragma unroll
        for (int i = 0; i < 4; i++) {
            int o = (to << 2) + i;
            float s = c1g[o] * INVS, b = c1b[o];
            float4 v;
            v.x = fmaxf(fmaf(a[i][0], s, b), 0.0f);
            v.y = fmaxf(fmaf(a[i][1], s, b), 0.0f);
            v.z = fmaxf(fmaf(a[i][2], s, b), 0.0f);
            v.w = fmaxf(fmaf(a[i][3], s, b), 0.0f);
            *reinterpret_cast<float4*>(&Cs[o * 64 + (tn << 2)]) = v;
        }
    }
    __syncthreads();

    auto pf2 = [&](int q, int stg) {
        if (q < 12) {
            int pass = q >> 2, c0 = (q & 3) << 4, ooff = pass << 6;
            cp16(ws_s + (unsigned int)(stg * 1024 + cr * 64 + wc4) * 4,
                 W2 + (size_t)(c0 + cr) * 192 + ooff + wc4);
        }
        cp_commit();
    };
    pf2(0, 0); pf2(1, 1);
    st = 0;
    for (int pass = 0; pass < 3; pass++) {
        unsigned long long a2[2][4];
        #pragma unroll
        for (int p = 0; p < 2; p++)
            #pragma unroll
            for (int j = 0; j < 4; j++) a2[p][j] = 0ull;
        for (int cq = 0; cq < 4; cq++) {
            int q = pass * 4 + cq;
            cp_wait<1>();
            __syncthreads();
            pf2(q + 2, (st + 2) % 3);
            #pragma unroll
            for (int c = 0; c < 16; c++) {
                float4 xv = *reinterpret_cast<const float4*>(&Cs[((cq << 4) + c) * 64 + (tn << 2)]);
                unsigned long long xd0 = pack2(xv.x), xd1 = pack2(xv.y);
                unsigned long long xd2 = pack2(xv.z), xd3 = pack2(xv.w);
                ulonglong2 w = *reinterpret_cast<const ulonglong2*>(&WsP[(st * 16 + c) * 64 + (to << 2)]);
                ffma2(a2[0][0], w.x, xd0); ffma2(a2[0][1], w.x, xd1);
                ffma2(a2[0][2], w.x, xd2); ffma2(a2[0][3], w.x, xd3);
                ffma2(a2[1][0], w.y, xd0); ffma2(a2[1][1], w.y, xd1);
                ffma2(a2[1][2], w.y, xd2); ffma2(a2[1][3], w.y, xd3);
            }
            st = (st + 1) % 3;
        }
        float a[4][4];
        #pragma unroll
        for (int p = 0; p < 2; p++)
            #pragma unroll
            for (int j = 0; j < 4; j++) {
                a[2 * p][j]     = lo2(a2[p][j]);
                a[2 * p + 1][j] = hi2(a2[p][j]);
            }
        int ooff = pass << 6;
        #pragma unroll
        for (int i = 0; i < 4; i++) {
            int o = ooff + (to << 2) + i;
            float bb = c2bias[o];
            size_t ob = (size_t)g * 12288 + (size_t)o * 64 + (tn << 2);
            float4 xin = *reinterpret_cast<const float4*>(&cat[ob]);
            float4 r;
            r.x = xin.x / (1.0f + expf(-(a[i][0] + bb)));
            r.y = xin.y / (1.0f + expf(-(a[i][1] + bb)));
            r.z = xin.z / (1.0f + expf(-(a[i][2] + bb)));
            r.w = xin.w / (1.0f + expf(-(a[i][3] + bb)));
            *reinterpret_cast<float4*>(&cat[ob]) = r;
        }
    }
}

// ---------------------------------------------------------------------------
// Fused GEMM, o-paired FFMA2, fully constexpr strides + constant-stage pipeline.
//   EPI: 1 relu(bn) | 3 relu(bn)+max-over-col | 4 red | 5 bias+relu |
//        6 final bn2(x1+acc+b) | 7 EdgeConv fused gather-max
// ---------------------------------------------------------------------------
#define MAINSTEP(S)                                                             \
    {                                                                           \
        cp_wait<1>();                                                           \
        __syncthreads();                                                        \
        prefetch(cb + 2, ((S) + 2) % 3);                                        \
        _Pragma("unroll")                                                       \
        for (int c = 0; c < 16; c++) {                                          \
            float4 xv = *reinterpret_cast<const float4*>(                       \
                &XsP[((S) * 16 + c) * 64 + (tn << 2)]);                         \
            unsigned long long xd0 = pack2(xv.x), xd1 = pack2(xv.y);            \
            unsigned long long xd2 = pack2(xv.z), xd3 = pack2(xv.w);            \
            const ulonglong2* wr = reinterpret_cast<const ulonglong2*>(         \
                &WsP[((S) * 16 + c) * OT + to * OPT]);                          \
            ulonglong2 w0 = wr[0];                                              \
            ffma2(acc2[0][0], w0.x, xd0); ffma2(acc2[0][1], w0.x, xd1);         \
            ffma2(acc2[0][2], w0.x, xd2); ffma2(acc2[0][3], w0.x, xd3);         \
            ffma2(acc2[1][0], w0.y, xd0); ffma2(acc2[1][1], w0.y, xd1);         \
            ffma2(acc2[1][2], w0.y, xd2); ffma2(acc2[1][3], w0.y, xd3);         \
            if constexpr (PAIRS == 4) {                                         \
                ulonglong2 w1 = wr[1];                                          \
                ffma2(acc2[2][0], w1.x, xd0); ffma2(acc2[2][1], w1.x, xd1);     \
                ffma2(acc2[2][2], w1.x, xd2); ffma2(acc2[2][3], w1.x, xd3);     \
                ffma2(acc2[3][0], w1.y, xd0); ffma2(acc2[3][1], w1.y, xd1);     \
                ffma2(acc2[3][2], w1.y, xd2); ffma2(acc2[3][3], w1.y, xd3);     \
            }                                                                   \
        }                                                                       \
        cb++;                                                                   \
    }

template<int EPI, int OT, int CIN, int WO, int XS, int XCPI, int OS, int OCPI, int CHOFF>
__global__ void __launch_bounds__(256)
gemm_k(const float* __restrict__ X, const float* __restrict__ Wt,
       float* out,
       const float* p0, const float* p1, const float* p2, const float* p3,
       const float* aux) {
    constexpr int OPT = OT / 16;
    constexpr int PAIRS = OPT / 2;
    constexpr int NCH = CIN / 16, REPS = NCH / 3, REM = NCH % 3;
    constexpr int PIPE_F = 3 * 16 * 64 + 3 * 16 * OT;
    constexpr int EPI7_F = (EPI == 7) ? (4096 + 4096 + 64 * 17) : 0;
    constexpr int SM_F = PIPE_F > EPI7_F ? PIPE_F : EPI7_F;
    __shared__ __align__(16) float smbuf[SM_F];
    float* XsP = smbuf;
    float* WsP = smbuf + 3 * 16 * 64;

    const int g = blockIdx.x;
    const int colBase = blockIdx.y << 6;
    const int oBase = blockIdx.z * OT;
    const int t = threadIdx.x;
    const int tn = t & 15, to = t >> 4;

    const float* Xg = X + (size_t)g * XS + colBase;
    const int cr = t >> 4;
    const int xc = (t & 15) << 2;
    const unsigned int xs_s = (unsigned int)__cvta_generic_to_shared(XsP);
    const unsigned int ws_s = (unsigned int)__cvta_generic_to_shared(WsP);

    unsigned long long acc2[PAIRS][4];
    #pragma unroll
    for (int p = 0; p < PAIRS; p++)
        #pragma unroll
        for (int j = 0; j < 4; j++) acc2[p][j] = 0ull;

    auto prefetch = [&](int cb, int stg) {
        if (cb < NCH) {
            const int c0 = cb << 4;
            cp16(xs_s + (unsigned int)(stg * 1024 + cr * 64 + xc) * 4,
                 Xg + (size_t)(c0 + cr) * XCPI + xc);
            const float* wrow = Wt + (size_t)(c0 + cr) * WO + oBase;
            if constexpr (OT == 128) {
                const int wc = (t & 15) << 3;
                cp16(ws_s + (unsigned int)(stg * 16 * OT + cr * OT + wc) * 4, wrow + wc);
                cp16(ws_s + (unsigned int)(stg * 16 * OT + cr * OT + wc + 4) * 4, wrow + wc + 4);
            } else {
                const int wc = (t & 15) << 2;
                cp16(ws_s + (unsigned int)(stg * 16 * OT + cr * OT + wc) * 4, wrow + wc);
            }
        }
        cp_commit();
    };

    prefetch(0, 0);
    prefetch(1, 1);

    int cb = 0;
    #pragma unroll 1
    for (int rep = 0; rep < REPS; rep++) {
        MAINSTEP(0)
        MAINSTEP(1)
        MAINSTEP(2)
    }
    if constexpr (REM >= 1) { MAINSTEP(0) }
    if constexpr (REM >= 2) { MAINSTEP(1) }

    float acc[OPT][4];
    #pragma unroll
    for (int p = 0; p < PAIRS; p++)
        #pragma unroll
        for (int j = 0; j < 4; j++) {
            acc[2 * p][j]     = lo2(acc2[p][j]);
            acc[2 * p + 1][j] = hi2(acc2[p][j]);
        }
    const float INVS = rsqrtf(1.0f + 1e-5f);

    if constexpr (EPI == 7) {
        float* Us = smbuf;
        float* Ts = smbuf + 4096;
        int*   sidx = (int*)(smbuf + 8192);
        __syncthreads();
        #pragma unroll
        for (int i = 0; i < OPT; i++) {
            int r = to * OPT + i;
            float* dst = (r < 64) ? &Us[r * 64] : &Ts[(r - 64) * 64];
            #pragma unroll
            for (int j = 0; j < 4; j++) dst[(tn << 2) + j] = acc[i][j];
        }
        const int* idg = d_idx_ + g * 1024;
        for (int i = t; i < 1024; i += 256)
            sidx[(i >> 4) * 17 + (i & 15)] = idg[i];
        __syncthreads();

        const int bnoff = blockIdx.z << 6;
        float* outg = out + (size_t)g * OS + (size_t)(CHOFF + bnoff) * OCPI;
        for (int item = t; item < 4096; item += 256) {
            int o = item >> 6, n = item & 63;
            float T = Ts[o * 64 + n];
            float s = p0[bnoff + o] * INVS, b = p1[bnoff + o];
            const float* Uo = &Us[o * 64];
            const int*   ni = &sidx[n * 17];
            float m = -FLT_MAX;
            #pragma unroll
            for (int k = 0; k < 16; k++) {
                float v = fmaf(Uo[ni[k]] + T, s, b);
                m = fmaxf(m, fmaxf(v, 0.0f));
            }
            outg[o * (size_t)OCPI + n] = m;
        }
    } else if constexpr (EPI == 3) {
        float* red = smbuf;
        __syncthreads();
        #pragma unroll
        for (int i = 0; i < OPT; i++) {
            int o = oBase + to * OPT + i;
            float s = p0[o] * INVS, b = p1[o];
            float m = -FLT_MAX;
            #pragma unroll
            for (int j = 0; j < 4; j++)
                m = fmaxf(m, fmaxf(fmaf(acc[i][j], s, b), 0.0f));
            red[(to * OPT + i) * 17 + tn] = m;
        }
        __syncthreads();
        if (t < OT) {
            float m = red[t * 17];
            #pragma unroll
            for (int q = 1; q < 16; q++) m = fmaxf(m, red[t * 17 + q]);
            int bb = g >> 8, mm = g & 255;   // g = b*256 + m
            out[((size_t)bb * 512 + oBase + t) * 256 + mm] = m;
        }
    } else {
        #pragma unroll
        for (int i = 0; i < OPT; i++) {
            int o = oBase + to * OPT + i;
            size_t ob = (size_t)g * OS + (size_t)(CHOFF + o) * OCPI
                      + colBase + (tn << 2);
            if constexpr (EPI == 1) {
                float s = p0[o] * INVS, b = p1[o];
                #pragma unroll
                for (int j = 0; j < 4; j++)
                    out[ob + j] = fmaxf(fmaf(acc[i][j], s, b), 0.0f);
            } else if constexpr (EPI == 4) {
                float sr = p0[o] * INVS, br = p1[o];
                float s1 = p2[o] * INVS, b1 = p3[o];
                #pragma unroll
                for (int j = 0; j < 4; j++) {
                    float r = fmaxf(fmaf(acc[i][j], sr, br), 0.0f);
                    out[ob + j] = fmaf(2.0f * r, s1, b1);
                }
            } else if constexpr (EPI == 5) {
                float bb = p0[o];
                #pragma unroll
                for (int j = 0; j < 4; j++)
                    out[ob + j] = fmaxf(acc[i][j] + bb, 0.0f);
            } else if constexpr (EPI == 6) {
                float bb = p0[o], s2 = p1[o] * INVS, b2 = p2[o];
                #pragma unroll
                for (int j = 0; j < 4; j++) {
                    float v = acc[i][j] + bb + aux[ob + j];
                    out[ob + j] = fmaf(v, s2, b2);
                }
            }
        }
    }
}

// ---------------------------------------------------------------------------
extern "C" void kernel_launch(void* const* d_in, const int* in_sizes, int n_in,
                              void* d_out, int out_size) {
    const float* xyz       = (const float*)d_in[0];
    const float* feats     = (const float*)d_in[1];
    const float* e1_w      = (const float*)d_in[2];
    const float* e1_g      = (const float*)d_in[3];
    const float* e1_b      = (const float*)d_in[4];
    const float* e2_w      = (const float*)d_in[5];
    const float* e2_g      = (const float*)d_in[6];
    const float* e2_b      = (const float*)d_in[7];
    const float* cal1_w    = (const float*)d_in[8];
    const float* cal1_g    = (const float*)d_in[9];
    const float* cal1_b    = (const float*)d_in[10];
    const float* cal2_w    = (const float*)d_in[11];
    const float* cal2_bias = (const float*)d_in[12];
    const float* exp1_w    = (const float*)d_in[13];
    const float* exp1_g    = (const float*)d_in[14];
    const float* exp1_b    = (const float*)d_in[15];
    const float* exp2_w    = (const float*)d_in[16];
    const float* exp2_g    = (const float*)d_in[17];
    const float* exp2_b    = (const float*)d_in[18];
    const float* red_w     = (const float*)d_in[19];
    const float* red_g     = (const float*)d_in[20];
    const float* red_b     = (const float*)d_in[21];
    const float* sc1_w     = (const float*)d_in[22];
    const float* sc1_b     = (const float*)d_in[23];
    const float* sc2_w     = (const float*)d_in[24];
    const float* sc2_b     = (const float*)d_in[25];
    const float* n1_g      = (const float*)d_in[26];
    const float* n1_b      = (const float*)d_in[27];
    const float* n2_g      = (const float*)d_in[28];
    const float* n2_b      = (const float*)d_in[29];

    float *dx, *dbig, *dcat, *dgt, *dx1, *dh, *dwt;
    cudaGetSymbolAddress((void**)&dx,   d_x_);
    cudaGetSymbolAddress((void**)&dbig, d_big_);
    cudaGetSymbolAddress((void**)&dcat, d_cat_);
    cudaGetSymbolAddress((void**)&dgt,  d_gt_);
    cudaGetSymbolAddress((void**)&dx1,  d_x1_);
    cudaGetSymbolAddress((void**)&dh,   d_h_);
    cudaGetSymbolAddress((void**)&dwt,  d_wt_);

    prep_pack<<<(WP_EXP2 + 255) / 256, 256>>>(e1_w, e2_w, cal1_w, cal2_w, exp1_w,
                                              exp2_w, red_w, sc1_w, sc2_w, 0);
    prep_pack<<<(WP_TOT - WP_EXP2 + 255) / 256, 256>>>(e1_w, e2_w, cal1_w, cal2_w, exp1_w,
                                                       exp2_w, red_w, sc1_w, sc2_w, 1);
    knn_kernel<<<512, 64>>>(xyz, feats);

    // EdgeConv1 fused (GEMM + gather-max) -> d_cat[0:64)
    gemm_k<7, 128, 64, 128, 4096, 64, 12288, 64, 0>
        <<<dim3(512, 1, 1), 256>>>(dx, dwt + WP_WS1, dcat,
                                   e1_g, e1_b, nullptr, nullptr, nullptr);
    // EdgeConv2 fused -> d_cat[64:192)   (z: two [U;T] interleaved halves)
    gemm_k<7, 128, 64, 256, 12288, 64, 12288, 64, 64>
        <<<dim3(512, 1, 2), 256>>>(dcat, dwt + WP_WS2, dcat,
                                   e2_g, e2_b, nullptr, nullptr, nullptr);

    // fused calib (cal1 + cal2 + sigmoid gate, in-place on d_cat)
    calib_kernel<<<512, 256>>>(dcat, cal1_g, cal1_b, cal2_bias);

    // exp1: relu(bn(exp1@x))
    gemm_k<1, 128, 192, 256, 12288, 64, 16384, 64, 0>
        <<<dim3(512, 1, 2), 256>>>(dcat, dwt + WP_EXP1, dbig,
                                   exp1_g, exp1_b, nullptr, nullptr, nullptr);
    // exp2 + max over 64 points -> pooled [b][512][256]
    gemm_k<3, 128, 256, 512, 16384, 64, 0, 0, 0>
        <<<dim3(512, 1, 4), 256>>>(dbig, dwt + WP_EXP2, dgt,
                                   exp2_g, exp2_b, nullptr, nullptr, nullptr);

    // red: x1 = bn1( 2 * relu(bn(red@pooled)) )
    gemm_k<4, 64, 512, 256, 131072, 256, 65536, 256, 0>
        <<<dim3(2, 4, 4), 256>>>(dgt, dwt + WP_RED, dx1,
                                 red_g, red_b, n1_g, n1_b, nullptr);
    // sc1: h = relu(sc1@x1 + b)
    gemm_k<5, 64, 256, 256, 65536, 256, 65536, 256, 0>
        <<<dim3(2, 4, 4), 256>>>(dx1, dwt + WP_SC1, dh,
                                 sc1_b, nullptr, nullptr, nullptr, nullptr);
    // sc2 + residual + bn2 -> final output: p0=sc2_b, p1=n2_g, p2=n2_b, aux=x1
    gemm_k<6, 64, 256, 256, 65536, 256, 65536, 256, 0>
        <<<dim3(2, 4, 4), 256>>>(dh, dwt + WP_SC2, (float*)d_out,
                                 sc2_b, n2_g, n2_b, nullptr, dx1);
}